// round 2
// baseline (speedup 1.0000x reference)
#include <cuda_runtime.h>
#include <cuda_bf16.h>

// Problem constants
#define NROWS 65536
#define DDIM  64
#define KEMB  8192

// argmin-GEMM tile config (packed f32x2 version)
#define BM    128
#define BN    64
#define NTHREADS 256            // 16 tx  x 16 ty
#define NTILES (KEMB / BN)      // 128
#define SMEM_BYTES (DDIM*BM*4 + DDIM*BN*8)   // Zs 32KB + Esd(dup) 32KB = 64KB

// Output layout (flattened, fp32):
//   [0, N*D) quantized | [N*D] vq_loss | [N*D+1] commit_loss | [N*D+2, +N) idx
#define OUT_LOSS   (NROWS * DDIM)
#define OUT_IDX    (NROWS * DDIM + 2)
#define NPARTIAL   1024

typedef unsigned long long ull;

// Scratch (no allocations allowed)
__device__ float g_esq[KEMB];
__device__ int   g_idx[NROWS];
__device__ float g_partial[NPARTIAL];

// ---------------------------------------------------------------------------
// packed f32x2 helpers (sm_103a FFMA2 path — not emitted by ptxas from C++)
// ---------------------------------------------------------------------------
__device__ __forceinline__ ull fma2(ull a, ull b, ull c) {
    ull d;
    asm("fma.rn.f32x2 %0, %1, %2, %3;" : "=l"(d) : "l"(a), "l"(b), "l"(c));
    return d;
}
__device__ __forceinline__ ull add2(ull a, ull b) {
    ull d;
    asm("add.rn.f32x2 %0, %1, %2;" : "=l"(d) : "l"(a), "l"(b));
    return d;
}
__device__ __forceinline__ ull dup2(float x) {
    unsigned int b = __float_as_uint(x);
    return ((ull)b << 32) | (ull)b;
}
__device__ __forceinline__ float lo2(ull u) { return __uint_as_float((unsigned int)u); }
__device__ __forceinline__ float hi2(ull u) { return __uint_as_float((unsigned int)(u >> 32)); }

// ---------------------------------------------------------------------------
// Kernel 1: e_sq[k] = sum_d emb[k][d]^2  (sequential order, fp32)
// ---------------------------------------------------------------------------
__global__ void esq_kernel(const float* __restrict__ E) {
    int k = blockIdx.x * blockDim.x + threadIdx.x;
    if (k < KEMB) {
        const float* row = E + k * DDIM;
        float s = 0.f;
#pragma unroll
        for (int d = 0; d < DDIM; d++) {
            float v = row[d];
            s = fmaf(v, v, s);
        }
        g_esq[k] = s;
    }
}

// ---------------------------------------------------------------------------
// Kernel 2: per-row argmin over K of d2 = (z_sq - 2*dot) + e_sq
// BM=128 rows x BN=64 cols per tile, FFMA2 (2 rows per packed lane).
// ---------------------------------------------------------------------------
__global__ __launch_bounds__(NTHREADS, 2) void vq_argmin_kernel(
    const float* __restrict__ Z, const float* __restrict__ E)
{
    extern __shared__ char smem_raw[];
    float* Zs  = reinterpret_cast<float*>(smem_raw);            // [d][m]  d*128+m
    ull*   Esd = reinterpret_cast<ull*>(smem_raw + DDIM*BM*4);  // [d][n] dup pairs

    const int tid = threadIdx.x;
    const int tx  = tid & 15;        // column lane 0..15
    const int ty  = tid >> 4;        // row group 0..15 (8 rows each)
    const int rowBase = blockIdx.x * BM;

    // ---- stage Z tile transposed: thread = (row lm2, half of d) ----
    {
        const int lm2  = tid & 127;
        const int half = tid >> 7;          // 0..1 -> 32 d's
        const float4* zp = reinterpret_cast<const float4*>(
            Z + (size_t)(rowBase + lm2) * DDIM + half * 32);
#pragma unroll
        for (int q = 0; q < 8; q++) {
            float4 v = zp[q];
            int d0 = half * 32 + q * 4;
            Zs[(d0 + 0) * BM + lm2] = v.x;
            Zs[(d0 + 1) * BM + lm2] = v.y;
            Zs[(d0 + 2) * BM + lm2] = v.z;
            Zs[(d0 + 3) * BM + lm2] = v.w;
        }
    }
    __syncthreads();

    // ---- z_sq for this thread's 4 row-pairs (sequential d, packed) ----
    ull zsq2[4];
#pragma unroll
    for (int ip = 0; ip < 4; ip++) {
        ull s2 = 0;
        const int m = ty * 8 + 2 * ip;
#pragma unroll
        for (int d = 0; d < DDIM; d++) {
            ull z2 = *reinterpret_cast<const ull*>(&Zs[d * BM + m]);
            s2 = fma2(z2, z2, s2);
        }
        zsq2[ip] = s2;
    }

    float bestv[8];
    int   besti[8];
#pragma unroll
    for (int r = 0; r < 8; r++) { bestv[r] = 3.4e38f; besti[r] = 0; }

    const ull NEG2 = dup2(-2.0f);

    // E tile loader mapping: row lm (0..63), d-chunk dc (16 d's = 4 float4)
    const int lm = tid & 63;
    const int dc = tid >> 6;

    // prefetch first E tile
    float4 pre[4];
    {
        const float4* ep = reinterpret_cast<const float4*>(
            E + (size_t)lm * DDIM + dc * 16);
#pragma unroll
        for (int q = 0; q < 4; q++) pre[q] = ep[q];
    }

    for (int kt = 0; kt < NTILES; kt++) {
        // store prefetched tile as duplicated pairs
#pragma unroll
        for (int q = 0; q < 4; q++) {
            int d0 = dc * 16 + q * 4;
            Esd[(d0 + 0) * BN + lm] = dup2(pre[q].x);
            Esd[(d0 + 1) * BN + lm] = dup2(pre[q].y);
            Esd[(d0 + 2) * BN + lm] = dup2(pre[q].z);
            Esd[(d0 + 3) * BN + lm] = dup2(pre[q].w);
        }
        __syncthreads();

        if (kt + 1 < NTILES) {
            const float4* ep = reinterpret_cast<const float4*>(
                E + (size_t)((kt + 1) * BN + lm) * DDIM + dc * 16);
#pragma unroll
            for (int q = 0; q < 4; q++) pre[q] = ep[q];
        }

        ull acc2[4][4];
#pragma unroll
        for (int ip = 0; ip < 4; ip++)
#pragma unroll
            for (int j = 0; j < 4; j++) acc2[ip][j] = 0;

#pragma unroll 16
        for (int d = 0; d < DDIM; d++) {
            // A: 4 natural row-pairs (rows ty*8 .. ty*8+7)
            ulonglong2 za = *reinterpret_cast<const ulonglong2*>(&Zs[d * BM + ty * 8]);
            ulonglong2 zb = *reinterpret_cast<const ulonglong2*>(&Zs[d * BM + ty * 8 + 4]);
            ull a2[4] = {za.x, za.y, zb.x, zb.y};
            // B: 4 strided duplicated columns (conflict-free LDS.64)
            ull b2[4];
#pragma unroll
            for (int j = 0; j < 4; j++) b2[j] = Esd[d * BN + tx + 16 * j];
#pragma unroll
            for (int ip = 0; ip < 4; ip++)
#pragma unroll
                for (int j = 0; j < 4; j++)
                    acc2[ip][j] = fma2(a2[ip], b2[j], acc2[ip][j]);
        }

        // epilogue: d2 = fl(fl(z_sq - 2*dot) + e_sq), strict-< running min
#pragma unroll
        for (int j = 0; j < 4; j++) {
            const int col = kt * BN + tx + 16 * j;
            const ull es2 = dup2(g_esq[col]);
#pragma unroll
            for (int ip = 0; ip < 4; ip++) {
                ull t2 = fma2(NEG2, acc2[ip][j], zsq2[ip]);
                ull d2 = add2(t2, es2);
                float vlo = lo2(d2), vhi = hi2(d2);
                int r0 = 2 * ip, r1 = 2 * ip + 1;
                if (vlo < bestv[r0]) { bestv[r0] = vlo; besti[r0] = col; }
                if (vhi < bestv[r1]) { bestv[r1] = vhi; besti[r1] = col; }
            }
        }
        __syncthreads();
    }

    // ---- reduce across the 16 tx lanes (tie -> lowest index) ----
#pragma unroll
    for (int r = 0; r < 8; r++) {
        float v = bestv[r];
        int   x = besti[r];
#pragma unroll
        for (int off = 8; off >= 1; off >>= 1) {
            float ov = __shfl_down_sync(0xFFFFFFFFu, v, off, 16);
            int   ox = __shfl_down_sync(0xFFFFFFFFu, x, off, 16);
            if (ov < v || (ov == v && ox < x)) { v = ov; x = ox; }
        }
        if (tx == 0) g_idx[rowBase + ty * 8 + r] = x;
    }
}

// ---------------------------------------------------------------------------
// Kernel 3: gather quantized = emb[idx], partial loss sums, index-as-float
// ---------------------------------------------------------------------------
__global__ __launch_bounds__(256) void gather_loss_kernel(
    const float* __restrict__ Z, const float* __restrict__ E,
    float* __restrict__ out)
{
    __shared__ float red[256];
    const int tid  = threadIdx.x;
    const int gtid = blockIdx.x * blockDim.x + tid;

    float lsum = 0.f;
    const float4* Z4 = reinterpret_cast<const float4*>(Z);
    float4* O4 = reinterpret_cast<float4*>(out);

#pragma unroll
    for (int j = 0; j < 4; j++) {
        int f   = gtid * 4 + j;
        int row = f >> 4;
        int dc  = (f & 15);
        int idx = g_idx[row];
        const float4* E4 = reinterpret_cast<const float4*>(E + (size_t)idx * DDIM);
        float4 q = E4[dc];
        float4 z = Z4[f];
        O4[f] = q;
        float dx = z.x - q.x, dy = z.y - q.y, dz = z.z - q.z, dw = z.w - q.w;
        lsum += dx * dx + dy * dy + dz * dz + dw * dw;
    }

    if (gtid < NROWS) out[OUT_IDX + gtid] = (float)g_idx[gtid];

    red[tid] = lsum;
    __syncthreads();
    for (int s = 128; s > 0; s >>= 1) {
        if (tid < s) red[tid] += red[tid + s];
        __syncthreads();
    }
    if (tid == 0) g_partial[blockIdx.x] = red[0];
}

// ---------------------------------------------------------------------------
// Kernel 4: finalize losses (single block, deterministic)
// ---------------------------------------------------------------------------
__global__ __launch_bounds__(512) void finalize_kernel(float* __restrict__ out) {
    __shared__ float red[512];
    int tid = threadIdx.x;
    red[tid] = g_partial[tid] + g_partial[tid + 512];
    __syncthreads();
    for (int s = 256; s > 0; s >>= 1) {
        if (tid < s) red[tid] += red[tid + s];
        __syncthreads();
    }
    if (tid == 0) {
        float loss = red[0] * (1.0f / (float)(NROWS * DDIM)); // N*D = 2^22, exact
        out[OUT_LOSS + 0] = loss;
        out[OUT_LOSS + 1] = loss;
    }
}

// ---------------------------------------------------------------------------
extern "C" void kernel_launch(void* const* d_in, const int* in_sizes, int n_in,
                              void* d_out, int out_size)
{
    const float* Z = (const float*)d_in[0];
    const float* E = (const float*)d_in[1];
    if (n_in >= 2 && in_sizes[0] == KEMB * DDIM && in_sizes[1] == NROWS * DDIM) {
        const float* t = Z; Z = E; E = t;
    }
    float* out = (float*)d_out;

    cudaFuncSetAttribute(vq_argmin_kernel,
                         cudaFuncAttributeMaxDynamicSharedMemorySize, SMEM_BYTES);

    esq_kernel<<<KEMB / 256, 256>>>(E);
    vq_argmin_kernel<<<NROWS / BM, NTHREADS, SMEM_BYTES>>>(Z, E);
    gather_loss_kernel<<<NPARTIAL, 256>>>(Z, E, out);
    finalize_kernel<<<1, 512>>>(out);
}

// round 4
// speedup vs baseline: 1.7416x; 1.7416x over previous
#include <cuda_runtime.h>
#include <cstdint>

// Problem constants
#define NROWS 65536
#define DDIM  64
#define KEMB  8192

#define BM 128
#define BN 128
#define NTILES (KEMB / BN)      // 64
#define NTHREADS 256            // 8 warps: 4 row-groups x 2 col-groups

// Output layout (flattened fp32): quantized | vq_loss | commit_loss | idx
#define OUT_LOSS   (NROWS * DDIM)
#define OUT_IDX    (NROWS * DDIM + 2)
#define NPARTIAL   1024

// smem byte offsets (pad-68 float rows: 128*68*4 = 34816 B per array)
#define SM_ZH   0
#define SM_ZL   34816
#define SM_B0   69632          // EH0 | EL0 (34816 each)
#define SM_B1   139264         // EH1 | EL1
#define SM_ES   208896         // 2 x 128 floats
#define SM_ZSQ  209920         // 128 floats
#define SM_RV   210432         // 128 floats
#define SM_RI   210944         // 128 ints
#define SMEM_TOTAL 211456

// scratch
__device__ float g_esq[KEMB];
__device__ int   g_idx[NROWS];
__device__ float g_partial[NPARTIAL];

// ---------------------------------------------------------------------------
__device__ __forceinline__ float tf32r(float x) {
    uint32_t y;
    asm("cvt.rna.tf32.f32 %0, %1;" : "=r"(y) : "f"(x));
    return __uint_as_float(y);
}

__device__ __forceinline__ void mma8(float c[4], const uint32_t a[4],
                                     uint32_t b0, uint32_t b1) {
    asm volatile(
        "mma.sync.aligned.m16n8k8.row.col.f32.tf32.tf32.f32 "
        "{%0,%1,%2,%3},{%4,%5,%6,%7},{%8,%9},{%0,%1,%2,%3};"
        : "+f"(c[0]), "+f"(c[1]), "+f"(c[2]), "+f"(c[3])
        : "r"(a[0]), "r"(a[1]), "r"(a[2]), "r"(a[3]), "r"(b0), "r"(b1));
}

// split a float4 into tf32 hi/lo float4s
__device__ __forceinline__ void split4(float4 v, float4& h, float4& l) {
    h.x = tf32r(v.x); l.x = tf32r(v.x - h.x);
    h.y = tf32r(v.y); l.y = tf32r(v.y - h.y);
    h.z = tf32r(v.z); l.z = tf32r(v.z - h.z);
    h.w = tf32r(v.w); l.w = tf32r(v.w - h.w);
}

// ---------------------------------------------------------------------------
// Kernel 1: e_sq (sequential fp32 chain)
// ---------------------------------------------------------------------------
__global__ void esq_kernel(const float* __restrict__ E) {
    int k = blockIdx.x * blockDim.x + threadIdx.x;
    if (k < KEMB) {
        const float* row = E + k * DDIM;
        float s = 0.f;
#pragma unroll
        for (int d = 0; d < DDIM; d++) s = fmaf(row[d], row[d], s);
        g_esq[k] = s;
    }
}

// ---------------------------------------------------------------------------
// Kernel 2: legacy mma.sync tf32 3-split argmin GEMM
// ---------------------------------------------------------------------------
__global__ __launch_bounds__(NTHREADS, 1) void vq_mma_kernel(
    const float* __restrict__ Z, const float* __restrict__ E)
{
    extern __shared__ __align__(16) char sm[];
    float* ZH  = reinterpret_cast<float*>(sm + SM_ZH);
    float* ZL  = reinterpret_cast<float*>(sm + SM_ZL);
    float* ES  = reinterpret_cast<float*>(sm + SM_ES);
    float* ZSQ = reinterpret_cast<float*>(sm + SM_ZSQ);
    float* RV  = reinterpret_cast<float*>(sm + SM_RV);
    int*   RI  = reinterpret_cast<int*>(sm + SM_RI);

    const int tid  = threadIdx.x;
    const int lane = tid & 31;
    const int warp = tid >> 5;
    const int cg   = warp & 1;          // col group (0/1) -> 64 cols
    const int rw   = warp >> 1;         // row group (0..3) -> 32 rows
    const int g    = lane >> 2;         // 0..7
    const int tq   = lane & 3;          // 0..3
    const int rowBase = blockIdx.x * BM;

    // ---- stage A (Z tile) split hi/lo, pad-68 rows ----
    {
        const float4* zp = reinterpret_cast<const float4*>(Z + (size_t)rowBase * DDIM);
#pragma unroll
        for (int i = 0; i < 8; i++) {
            int c = tid + i * 256;          // 0..2047
            int m = c >> 4, kc = c & 15;
            float4 h, l;
            split4(zp[c], h, l);
            *reinterpret_cast<float4*>(&ZH[m * 68 + kc * 4]) = h;
            *reinterpret_cast<float4*>(&ZL[m * 68 + kc * 4]) = l;
        }
    }
    // ---- zsq: exact sequential fp32 chain ----
    if (tid < BM) {
        const float* zr = Z + (size_t)(rowBase + tid) * DDIM;
        float s = 0.f;
#pragma unroll
        for (int d = 0; d < DDIM; d++) s = fmaf(zr[d], zr[d], s);
        ZSQ[tid] = s;
    }
    // ---- stage B tile 0 + es(0) ----
    {
        const float4* ep = reinterpret_cast<const float4*>(E);
        float* EH = reinterpret_cast<float*>(sm + SM_B0);
        float* EL = EH + 128 * 68;
#pragma unroll
        for (int i = 0; i < 8; i++) {
            int c = tid + i * 256;
            int n = c >> 4, kc = c & 15;
            float4 h, l;
            split4(ep[c], h, l);
            *reinterpret_cast<float4*>(&EH[n * 68 + kc * 4]) = h;
            *reinterpret_cast<float4*>(&EL[n * 68 + kc * 4]) = l;
        }
        if (tid < 32)
            reinterpret_cast<float4*>(ES)[tid] =
                reinterpret_cast<const float4*>(g_esq)[tid];
    }
    __syncthreads();

    // per-thread zsq values for its 4 rows
    float zsqv[4];
#pragma unroll
    for (int ri = 0; ri < 4; ri++)
        zsqv[ri] = ZSQ[rw * 32 + (ri >> 1) * 16 + g + (ri & 1) * 8];

    float bv[4]; int bi[4];
#pragma unroll
    for (int ri = 0; ri < 4; ri++) { bv[ri] = 3.4e38f; bi[ri] = 0; }

    float4 pf[8];
    float4 esf = make_float4(0.f, 0.f, 0.f, 0.f);

    for (int t = 0; t < NTILES; t++) {
        const float* EH = reinterpret_cast<const float*>(sm + ((t & 1) ? SM_B1 : SM_B0));
        const float* EL = EH + 128 * 68;
        const float* EST = ES + (t & 1) * 128;

        // prefetch next E tile (raw) + es into registers
        if (t + 1 < NTILES) {
            const float4* ep = reinterpret_cast<const float4*>(
                E + (size_t)(t + 1) * BN * DDIM);
#pragma unroll
            for (int i = 0; i < 8; i++) pf[i] = ep[tid + i * 256];
            if (tid < 32)
                esf = reinterpret_cast<const float4*>(g_esq + (size_t)(t + 1) * BN)[tid];
        }

        // ---- MMA block: 2 mfrags x 8 nfrags x 8 ksteps x 3 splits ----
        float acc[2][8][4];
#pragma unroll
        for (int mf = 0; mf < 2; mf++)
#pragma unroll
            for (int nf = 0; nf < 8; nf++)
#pragma unroll
                for (int j = 0; j < 4; j++) acc[mf][nf][j] = 0.f;

#pragma unroll
        for (int ks = 0; ks < 8; ks++) {
            uint32_t ah[2][4], al[2][4];
            const int k0 = ks * 8 + tq;
#pragma unroll
            for (int mf = 0; mf < 2; mf++) {
                const int r0 = rw * 32 + mf * 16 + g;
                ah[mf][0] = __float_as_uint(ZH[r0 * 68 + k0]);
                ah[mf][1] = __float_as_uint(ZH[(r0 + 8) * 68 + k0]);
                ah[mf][2] = __float_as_uint(ZH[r0 * 68 + k0 + 4]);
                ah[mf][3] = __float_as_uint(ZH[(r0 + 8) * 68 + k0 + 4]);
                al[mf][0] = __float_as_uint(ZL[r0 * 68 + k0]);
                al[mf][1] = __float_as_uint(ZL[(r0 + 8) * 68 + k0]);
                al[mf][2] = __float_as_uint(ZL[r0 * 68 + k0 + 4]);
                al[mf][3] = __float_as_uint(ZL[(r0 + 8) * 68 + k0 + 4]);
            }
#pragma unroll
            for (int nf = 0; nf < 8; nf++) {
                const int n0 = cg * 64 + nf * 8 + g;
                uint32_t eh0 = __float_as_uint(EH[n0 * 68 + k0]);
                uint32_t eh1 = __float_as_uint(EH[n0 * 68 + k0 + 4]);
                uint32_t el0 = __float_as_uint(EL[n0 * 68 + k0]);
                uint32_t el1 = __float_as_uint(EL[n0 * 68 + k0 + 4]);
#pragma unroll
                for (int mf = 0; mf < 2; mf++) {
                    mma8(acc[mf][nf], ah[mf], eh0, eh1);
                    mma8(acc[mf][nf], ah[mf], el0, el1);
                    mma8(acc[mf][nf], al[mf], eh0, eh1);
                }
            }
        }

        // ---- epilogue: d2 = fl(fl(zsq - 2 dot) + es), running min ----
        const int colT = t * BN + cg * 64;
#pragma unroll
        for (int nf = 0; nf < 8; nf++) {
            float2 ep2 = reinterpret_cast<const float2*>(EST)[cg * 32 + nf * 4 + tq];
#pragma unroll
            for (int mf = 0; mf < 2; mf++) {
#pragma unroll
                for (int j = 0; j < 4; j++) {
                    float es = (j & 1) ? ep2.y : ep2.x;
                    int ri = mf * 2 + (j >> 1);
                    float tt = fmaf(-2.0f, acc[mf][nf][j], zsqv[ri]);
                    float d2 = tt + es;
                    int col = colT + nf * 8 + 2 * tq + (j & 1);
                    if (d2 < bv[ri]) { bv[ri] = d2; bi[ri] = col; }
                }
            }
        }

        // ---- write staged next tile into the other buffer ----
        if (t + 1 < NTILES) {
            float* EHn = reinterpret_cast<float*>(sm + ((t & 1) ? SM_B0 : SM_B1));
            float* ELn = EHn + 128 * 68;
#pragma unroll
            for (int i = 0; i < 8; i++) {
                int c = tid + i * 256;
                int n = c >> 4, kc = c & 15;
                float4 h, l;
                split4(pf[i], h, l);
                *reinterpret_cast<float4*>(&EHn[n * 68 + kc * 4]) = h;
                *reinterpret_cast<float4*>(&ELn[n * 68 + kc * 4]) = l;
            }
            if (tid < 32)
                reinterpret_cast<float4*>(ES + ((t + 1) & 1) * 128)[tid] = esf;
        }
        __syncthreads();
    }

    // ---- reduce across the 4 lanes sharing each row (tie -> lowest col) ----
#pragma unroll
    for (int ri = 0; ri < 4; ri++) {
        float v = bv[ri];
        int   x = bi[ri];
#pragma unroll
        for (int off = 1; off <= 2; off <<= 1) {
            float ov = __shfl_xor_sync(0xFFFFFFFFu, v, off);
            int   ox = __shfl_xor_sync(0xFFFFFFFFu, x, off);
            if (ov < v || (ov == v && ox < x)) { v = ov; x = ox; }
        }
        bv[ri] = v; bi[ri] = x;
    }
    if (tq == 0 && cg == 0) {
#pragma unroll
        for (int ri = 0; ri < 4; ri++) {
            int row = rw * 32 + (ri >> 1) * 16 + g + (ri & 1) * 8;
            RV[row] = bv[ri]; RI[row] = bi[ri];
        }
    }
    __syncthreads();
    if (tq == 0 && cg == 1) {
#pragma unroll
        for (int ri = 0; ri < 4; ri++) {
            int row = rw * 32 + (ri >> 1) * 16 + g + (ri & 1) * 8;
            float v0 = RV[row]; int i0 = RI[row];
            int win = (bv[ri] < v0 || (bv[ri] == v0 && bi[ri] < i0)) ? bi[ri] : i0;
            g_idx[rowBase + row] = win;
        }
    }
}

// ---------------------------------------------------------------------------
// Kernel 3: gather + partial loss + index-as-float
// ---------------------------------------------------------------------------
__global__ __launch_bounds__(256) void gather_loss_kernel(
    const float* __restrict__ Z, const float* __restrict__ E,
    float* __restrict__ out)
{
    __shared__ float red[256];
    const int tid  = threadIdx.x;
    const int gtid = blockIdx.x * blockDim.x + tid;

    float lsum = 0.f;
    const float4* Z4 = reinterpret_cast<const float4*>(Z);
    float4* O4 = reinterpret_cast<float4*>(out);

#pragma unroll
    for (int j = 0; j < 4; j++) {
        int f   = gtid * 4 + j;
        int row = f >> 4;
        int dc  = (f & 15);
        int idx = g_idx[row];
        const float4* E4 = reinterpret_cast<const float4*>(E + (size_t)idx * DDIM);
        float4 q = E4[dc];
        float4 z = Z4[f];
        O4[f] = q;
        float dx = z.x - q.x, dy = z.y - q.y, dz = z.z - q.z, dw = z.w - q.w;
        lsum += dx * dx + dy * dy + dz * dz + dw * dw;
    }

    if (gtid < NROWS) out[OUT_IDX + gtid] = (float)g_idx[gtid];

    red[tid] = lsum;
    __syncthreads();
    for (int s = 128; s > 0; s >>= 1) {
        if (tid < s) red[tid] += red[tid + s];
        __syncthreads();
    }
    if (tid == 0) g_partial[blockIdx.x] = red[0];
}

// ---------------------------------------------------------------------------
// Kernel 4: finalize losses
// ---------------------------------------------------------------------------
__global__ __launch_bounds__(512) void finalize_kernel(float* __restrict__ out) {
    __shared__ float red[512];
    int tid = threadIdx.x;
    red[tid] = g_partial[tid] + g_partial[tid + 512];
    __syncthreads();
    for (int s = 256; s > 0; s >>= 1) {
        if (tid < s) red[tid] += red[tid + s];
        __syncthreads();
    }
    if (tid == 0) {
        float loss = red[0] * (1.0f / (float)(NROWS * DDIM)); // N*D = 2^22, exact
        out[OUT_LOSS + 0] = loss;
        out[OUT_LOSS + 1] = loss;
    }
}

// ---------------------------------------------------------------------------
extern "C" void kernel_launch(void* const* d_in, const int* in_sizes, int n_in,
                              void* d_out, int out_size)
{
    const float* Z = (const float*)d_in[0];
    const float* E = (const float*)d_in[1];
    if (n_in >= 2 && in_sizes[0] == KEMB * DDIM && in_sizes[1] == NROWS * DDIM) {
        const float* t = Z; Z = E; E = t;
    }
    float* out = (float*)d_out;

    cudaFuncSetAttribute(vq_mma_kernel,
                         cudaFuncAttributeMaxDynamicSharedMemorySize, SMEM_TOTAL);

    esq_kernel<<<KEMB / 256, 256>>>(E);
    vq_mma_kernel<<<NROWS / BM, NTHREADS, SMEM_TOTAL>>>(Z, E);
    gather_loss_kernel<<<NPARTIAL, 256>>>(Z, E, out);
    finalize_kernel<<<1, 512>>>(out);
}

// round 6
// speedup vs baseline: 1.8135x; 1.0413x over previous
#include <cuda_runtime.h>
#include <cstdint>

// Problem constants
#define NROWS 65536
#define DDIM  64
#define KEMB  8192

#define BM 128
#define BN 128
#define NTILES (KEMB / BN)      // 64
#define NTHREADS 256            // 8 warps: 4 row-groups x 2 col-groups

// Output layout (flattened fp32): quantized | vq_loss | commit_loss | idx
#define OUT_LOSS   (NROWS * DDIM)
#define OUT_IDX    (NROWS * DDIM + 2)
#define NPARTIAL   1024

// smem byte offsets
#define SM_B0   0               // 32768 (128x64 f32, swizzled)
#define SM_B1   32768           // 32768
#define SM_Z    65536           // 34816 (128 x 68 f32, padded)
#define SM_ALO  100352          // 32768 (A-lo fragments, [ks][mf][rw][lane][4])
#define SM_ES   133120          // 1024  (2 x 128 f32)
#define SM_ZSQ  134144          // 512
#define SM_RV   134656          // 512
#define SM_RI   135168          // 512
#define SMEM_TOTAL 135680

// scratch
__device__ float g_esq[KEMB];
__device__ int   g_idx[NROWS];
__device__ float g_partial[NPARTIAL];

// ---------------------------------------------------------------------------
__device__ __forceinline__ float tf32r(float x) {
    uint32_t y;
    asm("cvt.rna.tf32.f32 %0, %1;" : "=r"(y) : "f"(x));
    return __uint_as_float(y);
}
__device__ __forceinline__ void mma8(float c[4], const uint32_t a[4],
                                     uint32_t b0, uint32_t b1) {
    asm volatile(
        "mma.sync.aligned.m16n8k8.row.col.f32.tf32.tf32.f32 "
        "{%0,%1,%2,%3},{%4,%5,%6,%7},{%8,%9},{%0,%1,%2,%3};"
        : "+f"(c[0]), "+f"(c[1]), "+f"(c[2]), "+f"(c[3])
        : "r"(a[0]), "r"(a[1]), "r"(a[2]), "r"(a[3]), "r"(b0), "r"(b1));
}
__device__ __forceinline__ uint32_t smem_u32(const void* p) {
    uint32_t a;
    asm("{ .reg .u64 t; cvta.to.shared.u64 t, %1; cvt.u32.u64 %0, t; }"
        : "=r"(a) : "l"(p));
    return a;
}
__device__ __forceinline__ void cp16(uint32_t dst, const void* src) {
    asm volatile("cp.async.cg.shared.global [%0], [%1], 16;"
                 :: "r"(dst), "l"(src) : "memory");
}
#define CP_COMMIT() asm volatile("cp.async.commit_group;" ::: "memory")
#define CP_WAIT1()  asm volatile("cp.async.wait_group 1;" ::: "memory")
#define CP_WAIT0()  asm volatile("cp.async.wait_group 0;" ::: "memory")

// B swizzle: float index within tile for logical (n, k)
__device__ __forceinline__ int bswz(int n, int k) {
    return n * 64 + (k ^ ((n & 3) << 3) ^ (n & 4));
}

// ---------------------------------------------------------------------------
// Kernel 1: e_sq (sequential fp32 chain)
// ---------------------------------------------------------------------------
__global__ void esq_kernel(const float* __restrict__ E) {
    int k = blockIdx.x * blockDim.x + threadIdx.x;
    if (k < KEMB) {
        const float* row = E + k * DDIM;
        float s = 0.f;
#pragma unroll
        for (int d = 0; d < DDIM; d++) s = fmaf(row[d], row[d], s);
        g_esq[k] = s;
    }
}

// ---------------------------------------------------------------------------
// Kernel 2: tf32 3-split argmin GEMM, cp.async pipelined, A-hi in registers
// ---------------------------------------------------------------------------
__global__ __launch_bounds__(NTHREADS, 1) void vq_mma_kernel(
    const float* __restrict__ Z, const float* __restrict__ E)
{
    extern __shared__ __align__(16) char sm[];
    float* Zs  = reinterpret_cast<float*>(sm + SM_Z);
    float* ALO = reinterpret_cast<float*>(sm + SM_ALO);
    float* ES  = reinterpret_cast<float*>(sm + SM_ES);
    float* ZSQ = reinterpret_cast<float*>(sm + SM_ZSQ);
    float* RV  = reinterpret_cast<float*>(sm + SM_RV);
    int*   RI  = reinterpret_cast<int*>(sm + SM_RI);
    const uint32_t smb = smem_u32(sm);

    const int tid  = threadIdx.x;
    const int lane = tid & 31;
    const int warp = tid >> 5;
    const int cg   = warp & 1;          // col group (0/1) -> 64 cols
    const int rw   = warp >> 1;         // row group (0..3) -> 32 rows
    const int g    = lane >> 2;         // 0..7
    const int tq   = lane & 3;          // 0..3
    const int rowBase = blockIdx.x * BM;

    // ---- issue cp.async for B tiles 0 and 1 (+ es) ----
    {
        const int n  = tid >> 4;
        const int kq = (tid & 15) * 4;
        const uint32_t doff = (uint32_t)(bswz(n, kq) * 4);
        cp16(smb + SM_B0 + doff, E + (size_t)n * DDIM + kq);
        cp16(smb + SM_B1 + doff, E + (size_t)(BN + n) * DDIM + kq);
    }
    {
#pragma unroll
        for (int i = 1; i < 8; i++) {
            int c  = tid + i * 256;
            int n  = c >> 4;
            int kq = (c & 15) * 4;
            uint32_t doff = (uint32_t)(bswz(n, kq) * 4);
            cp16(smb + SM_B0 + doff, E + (size_t)n * DDIM + kq);
        }
        if (tid < 32)
            cp16(smb + SM_ES + tid * 16, g_esq + tid * 4);
        CP_COMMIT();
#pragma unroll
        for (int i = 1; i < 8; i++) {
            int c  = tid + i * 256;
            int n  = c >> 4;
            int kq = (c & 15) * 4;
            uint32_t doff = (uint32_t)(bswz(n, kq) * 4);
            cp16(smb + SM_B1 + doff, E + (size_t)(BN + n) * DDIM + kq);
        }
        if (tid < 32)
            cp16(smb + SM_ES + 512 + tid * 16, g_esq + BN + tid * 4);
        CP_COMMIT();
    }

    // ---- stage Z tile (plain fp32, pad-68 rows) ----
    {
        const float4* zp = reinterpret_cast<const float4*>(Z + (size_t)rowBase * DDIM);
#pragma unroll
        for (int i = 0; i < 8; i++) {
            int c = tid + i * 256;
            int m = c >> 4, kc = c & 15;
            float4 v = zp[c];
            *reinterpret_cast<float4*>(&Zs[m * 68 + kc * 4]) = v;
        }
    }
    __syncthreads();

    // ---- zsq: exact sequential fp32 chain ----
    if (tid < BM) {
        float s = 0.f;
#pragma unroll
        for (int d = 0; d < DDIM; d++) {
            float v = Zs[tid * 68 + d];
            s = fmaf(v, v, s);
        }
        ZSQ[tid] = s;
    }

    // ---- build A fragments: hi in registers, lo to smem keyed by rw ----
    uint32_t ah[2][8][4];
#pragma unroll
    for (int mf = 0; mf < 2; mf++) {
        const int r0 = rw * 32 + mf * 16 + g;
#pragma unroll
        for (int ks = 0; ks < 8; ks++) {
            const int k0 = ks * 8 + tq;
            float f0 = Zs[r0 * 68 + k0];
            float f1 = Zs[(r0 + 8) * 68 + k0];
            float f2 = Zs[r0 * 68 + k0 + 4];
            float f3 = Zs[(r0 + 8) * 68 + k0 + 4];
            float h0 = tf32r(f0), h1 = tf32r(f1), h2 = tf32r(f2), h3 = tf32r(f3);
            ah[mf][ks][0] = __float_as_uint(h0);
            ah[mf][ks][1] = __float_as_uint(h1);
            ah[mf][ks][2] = __float_as_uint(h2);
            ah[mf][ks][3] = __float_as_uint(h3);
            float4 l = make_float4(f0 - h0, f1 - h1, f2 - h2, f3 - h3);
            // layout: [ks][mf][rw][lane], cg-twins write identical data (benign)
            *reinterpret_cast<float4*>(
                &ALO[(((ks * 2 + mf) * 4 + rw) * 32 + lane) * 4]) = l;
        }
    }
    __syncthreads();

    float zsqv[4];
#pragma unroll
    for (int ri = 0; ri < 4; ri++)
        zsqv[ri] = ZSQ[rw * 32 + (ri >> 1) * 16 + g + (ri & 1) * 8];

    float bv[4]; int bi[4];
#pragma unroll
    for (int ri = 0; ri < 4; ri++) { bv[ri] = 3.4e38f; bi[ri] = 0; }

    const int swz = ((g & 3) << 3) ^ (g & 4);   // per-lane B k-swizzle

    for (int t = 0; t < NTILES; t++) {
        if (t >= NTILES - 2) { CP_WAIT0(); } else { CP_WAIT1(); }
        __syncthreads();

        const float* B = reinterpret_cast<const float*>(sm + ((t & 1) ? SM_B1 : SM_B0));
        const float* EST = ES + (t & 1) * 128;

        float acc[2][8][4];
#pragma unroll
        for (int mf = 0; mf < 2; mf++)
#pragma unroll
            for (int nf = 0; nf < 8; nf++)
#pragma unroll
                for (int j = 0; j < 4; j++) acc[mf][nf][j] = 0.f;

#pragma unroll
        for (int ks = 0; ks < 8; ks++) {
            float4 al0 = *reinterpret_cast<const float4*>(
                &ALO[(((ks * 2 + 0) * 4 + rw) * 32 + lane) * 4]);
            float4 al1 = *reinterpret_cast<const float4*>(
                &ALO[(((ks * 2 + 1) * 4 + rw) * 32 + lane) * 4]);
            uint32_t alr[2][4] = {
                {__float_as_uint(al0.x), __float_as_uint(al0.y),
                 __float_as_uint(al0.z), __float_as_uint(al0.w)},
                {__float_as_uint(al1.x), __float_as_uint(al1.y),
                 __float_as_uint(al1.z), __float_as_uint(al1.w)}};
            const int k0s = (ks * 8 + tq) ^ swz;
#pragma unroll
            for (int nf = 0; nf < 8; nf++) {
                const int nb = (cg * 64 + nf * 8 + g) * 64;
                float b0f = B[nb + k0s];
                float b1f = B[nb + (k0s ^ 4)];
                float h0 = tf32r(b0f), h1 = tf32r(b1f);
                uint32_t eh0 = __float_as_uint(h0);
                uint32_t eh1 = __float_as_uint(h1);
                uint32_t el0 = __float_as_uint(b0f - h0);
                uint32_t el1 = __float_as_uint(b1f - h1);
#pragma unroll
                for (int mf = 0; mf < 2; mf++) {
                    mma8(acc[mf][nf], ah[mf][ks], eh0, eh1);
                    mma8(acc[mf][nf], ah[mf][ks], el0, el1);
                    mma8(acc[mf][nf], alr[mf],    eh0, eh1);
                }
            }
        }

        // ---- epilogue: d2 = fl(fl(zsq - 2 dot) + es), running min ----
        const int colT = t * BN + cg * 64;
#pragma unroll
        for (int nf = 0; nf < 8; nf++) {
            float2 ep2 = reinterpret_cast<const float2*>(EST)[cg * 32 + nf * 4 + tq];
#pragma unroll
            for (int mf = 0; mf < 2; mf++) {
#pragma unroll
                for (int j = 0; j < 4; j++) {
                    float es = (j & 1) ? ep2.y : ep2.x;
                    int ri = mf * 2 + (j >> 1);
                    float tt = fmaf(-2.0f, acc[mf][nf][j], zsqv[ri]);
                    float d2 = tt + es;
                    int col = colT + nf * 8 + 2 * tq + (j & 1);
                    if (d2 < bv[ri]) { bv[ri] = d2; bi[ri] = col; }
                }
            }
        }

        __syncthreads();

        // ---- issue cp.async for tile t+2 into the buffer just freed ----
        if (t + 2 < NTILES) {
            const uint32_t dbase = smb + ((t & 1) ? SM_B1 : SM_B0);
            const float* ebase = E + (size_t)(t + 2) * BN * DDIM;
#pragma unroll
            for (int i = 0; i < 8; i++) {
                int c  = tid + i * 256;
                int n  = c >> 4;
                int kq = (c & 15) * 4;
                cp16(dbase + (uint32_t)(bswz(n, kq) * 4), ebase + (size_t)n * DDIM + kq);
            }
            if (tid < 32)
                cp16(smb + SM_ES + (t & 1) * 512 + tid * 16,
                     g_esq + (size_t)(t + 2) * BN + tid * 4);
            CP_COMMIT();
        }
    }

    // ---- reduce across the 4 tq lanes sharing each row (tie -> lowest col) ----
#pragma unroll
    for (int ri = 0; ri < 4; ri++) {
        float v = bv[ri];
        int   x = bi[ri];
#pragma unroll
        for (int off = 1; off <= 2; off <<= 1) {
            float ov = __shfl_xor_sync(0xFFFFFFFFu, v, off);
            int   ox = __shfl_xor_sync(0xFFFFFFFFu, x, off);
            if (ov < v || (ov == v && ox < x)) { v = ov; x = ox; }
        }
        bv[ri] = v; bi[ri] = x;
    }
    if (tq == 0 && cg == 0) {
#pragma unroll
        for (int ri = 0; ri < 4; ri++) {
            int row = rw * 32 + (ri >> 1) * 16 + g + (ri & 1) * 8;
            RV[row] = bv[ri]; RI[row] = bi[ri];
        }
    }
    __syncthreads();
    if (tq == 0 && cg == 1) {
#pragma unroll
        for (int ri = 0; ri < 4; ri++) {
            int row = rw * 32 + (ri >> 1) * 16 + g + (ri & 1) * 8;
            float v0 = RV[row]; int i0 = RI[row];
            int win = (bv[ri] < v0 || (bv[ri] == v0 && bi[ri] < i0)) ? bi[ri] : i0;
            g_idx[rowBase + row] = win;
        }
    }
}

// ---------------------------------------------------------------------------
// Kernel 3: gather + partial loss + index-as-float
// ---------------------------------------------------------------------------
__global__ __launch_bounds__(256) void gather_loss_kernel(
    const float* __restrict__ Z, const float* __restrict__ E,
    float* __restrict__ out)
{
    __shared__ float red[256];
    const int tid  = threadIdx.x;
    const int gtid = blockIdx.x * blockDim.x + tid;

    float lsum = 0.f;
    const float4* Z4 = reinterpret_cast<const float4*>(Z);
    float4* O4 = reinterpret_cast<float4*>(out);

#pragma unroll
    for (int j = 0; j < 4; j++) {
        int f   = gtid * 4 + j;
        int row = f >> 4;
        int dc  = (f & 15);
        int idx = g_idx[row];
        const float4* E4 = reinterpret_cast<const float4*>(E + (size_t)idx * DDIM);
        float4 q = E4[dc];
        float4 z = Z4[f];
        O4[f] = q;
        float dx = z.x - q.x, dy = z.y - q.y, dz = z.z - q.z, dw = z.w - q.w;
        lsum += dx * dx + dy * dy + dz * dz + dw * dw;
    }

    if (gtid < NROWS) out[OUT_IDX + gtid] = (float)g_idx[gtid];

    red[tid] = lsum;
    __syncthreads();
    for (int s = 128; s > 0; s >>= 1) {
        if (tid < s) red[tid] += red[tid + s];
        __syncthreads();
    }
    if (tid == 0) g_partial[blockIdx.x] = red[0];
}

// ---------------------------------------------------------------------------
// Kernel 4: finalize losses
// ---------------------------------------------------------------------------
__global__ __launch_bounds__(512) void finalize_kernel(float* __restrict__ out) {
    __shared__ float red[512];
    int tid = threadIdx.x;
    red[tid] = g_partial[tid] + g_partial[tid + 512];
    __syncthreads();
    for (int s = 256; s > 0; s >>= 1) {
        if (tid < s) red[tid] += red[tid + s];
        __syncthreads();
    }
    if (tid == 0) {
        float loss = red[0] * (1.0f / (float)(NROWS * DDIM)); // N*D = 2^22, exact
        out[OUT_LOSS + 0] = loss;
        out[OUT_LOSS + 1] = loss;
    }
}

// ---------------------------------------------------------------------------
extern "C" void kernel_launch(void* const* d_in, const int* in_sizes, int n_in,
                              void* d_out, int out_size)
{
    const float* Z = (const float*)d_in[0];
    const float* E = (const float*)d_in[1];
    if (n_in >= 2 && in_sizes[0] == KEMB * DDIM && in_sizes[1] == NROWS * DDIM) {
        const float* t = Z; Z = E; E = t;
    }
    float* out = (float*)d_out;

    cudaFuncSetAttribute(vq_mma_kernel,
                         cudaFuncAttributeMaxDynamicSharedMemorySize, SMEM_TOTAL);

    esq_kernel<<<KEMB / 256, 256>>>(E);
    vq_mma_kernel<<<NROWS / BM, NTHREADS, SMEM_TOTAL>>>(Z, E);
    gather_loss_kernel<<<NPARTIAL, 256>>>(Z, E, out);
    finalize_kernel<<<1, 512>>>(out);
}

// round 7
// speedup vs baseline: 3.0684x; 1.6920x over previous
#include <cuda_runtime.h>
#include <cstdint>

// Problem constants
#define NROWS 65536
#define DDIM  64
#define KEMB  8192

#define BM 128
#define BN 128
#define NTILES (KEMB / BN)      // 64
#define NTHREADS 256            // 8 warps: 4 row-groups x 2 col-groups

// Output layout (flattened fp32): quantized | vq_loss | commit_loss | idx
#define OUT_LOSS   (NROWS * DDIM)
#define OUT_IDX    (NROWS * DDIM + 2)
#define NPARTIAL   1024

// smem byte offsets
#define SM_B0   0               // 32768 (128x64 f32, swizzled)
#define SM_B1   32768           // 32768
#define SM_Z    65536           // 34816 (128 x 68 f32, padded)
#define SM_ES   100352          // 1024  (2 x 128 f32)
#define SM_ZSQ  101376          // 512
#define SM_RV   101888          // 512
#define SM_RI   102400          // 512
#define SMEM_TOTAL 102912

// scratch
__device__ float g_esq[KEMB];
__device__ int   g_idx[NROWS];
__device__ float g_partial[NPARTIAL];

// ---------------------------------------------------------------------------
__device__ __forceinline__ uint32_t pack_bf16x2(float lo, float hi) {
    uint32_t d;
    asm("cvt.rn.bf16x2.f32 %0, %1, %2;" : "=r"(d) : "f"(hi), "f"(lo));
    return d;
}
__device__ __forceinline__ float bf_lo(uint32_t u) { return __uint_as_float(u << 16); }
__device__ __forceinline__ float bf_hi(uint32_t u) { return __uint_as_float(u & 0xffff0000u); }

// split a float pair into bf16x2 hi + bf16x2 lo(residual)
__device__ __forceinline__ void split_pair(float f0, float f1,
                                           uint32_t& h, uint32_t& l) {
    h = pack_bf16x2(f0, f1);
    l = pack_bf16x2(f0 - bf_lo(h), f1 - bf_hi(h));
}

__device__ __forceinline__ void mma16(float c[4], const uint32_t a[4],
                                      uint32_t b0, uint32_t b1) {
    asm volatile(
        "mma.sync.aligned.m16n8k16.row.col.f32.bf16.bf16.f32 "
        "{%0,%1,%2,%3},{%4,%5,%6,%7},{%8,%9},{%0,%1,%2,%3};"
        : "+f"(c[0]), "+f"(c[1]), "+f"(c[2]), "+f"(c[3])
        : "r"(a[0]), "r"(a[1]), "r"(a[2]), "r"(a[3]), "r"(b0), "r"(b1));
}
__device__ __forceinline__ uint32_t smem_u32(const void* p) {
    uint32_t a;
    asm("{ .reg .u64 t; cvta.to.shared.u64 t, %1; cvt.u32.u64 %0, t; }"
        : "=r"(a) : "l"(p));
    return a;
}
__device__ __forceinline__ void cp16(uint32_t dst, const void* src) {
    asm volatile("cp.async.cg.shared.global [%0], [%1], 16;"
                 :: "r"(dst), "l"(src) : "memory");
}
#define CP_COMMIT() asm volatile("cp.async.commit_group;" ::: "memory")
#define CP_WAIT1()  asm volatile("cp.async.wait_group 1;" ::: "memory")
#define CP_WAIT0()  asm volatile("cp.async.wait_group 0;" ::: "memory")

// B swizzle: float index within tile for logical (n, k)
__device__ __forceinline__ int bswz(int n, int k) {
    return n * 64 + (k ^ ((n & 3) << 3) ^ (n & 4));
}

// ---------------------------------------------------------------------------
// Kernel 1: e_sq (sequential fp32 chain)
// ---------------------------------------------------------------------------
__global__ void esq_kernel(const float* __restrict__ E) {
    int k = blockIdx.x * blockDim.x + threadIdx.x;
    if (k < KEMB) {
        const float* row = E + k * DDIM;
        float s = 0.f;
#pragma unroll
        for (int d = 0; d < DDIM; d++) s = fmaf(row[d], row[d], s);
        g_esq[k] = s;
    }
}

// ---------------------------------------------------------------------------
// Kernel 2: bf16 3-term split argmin GEMM, cp.async pipelined, A in registers
// ---------------------------------------------------------------------------
__global__ __launch_bounds__(NTHREADS, 1) void vq_mma_kernel(
    const float* __restrict__ Z, const float* __restrict__ E)
{
    extern __shared__ __align__(16) char sm[];
    float* Zs  = reinterpret_cast<float*>(sm + SM_Z);
    float* ES  = reinterpret_cast<float*>(sm + SM_ES);
    float* ZSQ = reinterpret_cast<float*>(sm + SM_ZSQ);
    float* RV  = reinterpret_cast<float*>(sm + SM_RV);
    int*   RI  = reinterpret_cast<int*>(sm + SM_RI);
    const uint32_t smb = smem_u32(sm);

    const int tid  = threadIdx.x;
    const int lane = tid & 31;
    const int warp = tid >> 5;
    const int cg   = warp & 1;          // col group (0/1) -> 64 cols
    const int rw   = warp >> 1;         // row group (0..3) -> 32 rows
    const int g    = lane >> 2;         // 0..7
    const int tq   = lane & 3;          // 0..3
    const int rowBase = blockIdx.x * BM;

    // ---- issue cp.async for B tiles 0 and 1 (+ es) ----
    {
#pragma unroll
        for (int i = 0; i < 8; i++) {
            int c  = tid + i * 256;
            int n  = c >> 4;
            int kq = (c & 15) * 4;
            uint32_t doff = (uint32_t)(bswz(n, kq) * 4);
            cp16(smb + SM_B0 + doff, E + (size_t)n * DDIM + kq);
        }
        if (tid < 32)
            cp16(smb + SM_ES + tid * 16, g_esq + tid * 4);
        CP_COMMIT();
#pragma unroll
        for (int i = 0; i < 8; i++) {
            int c  = tid + i * 256;
            int n  = c >> 4;
            int kq = (c & 15) * 4;
            uint32_t doff = (uint32_t)(bswz(n, kq) * 4);
            cp16(smb + SM_B1 + doff, E + (size_t)(BN + n) * DDIM + kq);
        }
        if (tid < 32)
            cp16(smb + SM_ES + 512 + tid * 16, g_esq + BN + tid * 4);
        CP_COMMIT();
    }

    // ---- stage Z tile (plain fp32, pad-68 rows) ----
    {
        const float4* zp = reinterpret_cast<const float4*>(Z + (size_t)rowBase * DDIM);
#pragma unroll
        for (int i = 0; i < 8; i++) {
            int c = tid + i * 256;
            int m = c >> 4, kc = c & 15;
            float4 v = zp[c];
            *reinterpret_cast<float4*>(&Zs[m * 68 + kc * 4]) = v;
        }
    }
    __syncthreads();

    // ---- zsq: exact sequential fp32 chain ----
    if (tid < BM) {
        float s = 0.f;
#pragma unroll
        for (int d = 0; d < DDIM; d++) {
            float v = Zs[tid * 68 + d];
            s = fmaf(v, v, s);
        }
        ZSQ[tid] = s;
    }

    // ---- build A fragments (bf16 hi + lo residual), all in registers ----
    // m16n8k16: a0={r0,k+2tq(+1)}, a1={r0+8,..}, a2={r0,k+2tq+8(+9)}, a3={r0+8,..}
    uint32_t ah[2][4][4], al[2][4][4];
#pragma unroll
    for (int mf = 0; mf < 2; mf++) {
        const int r0 = rw * 32 + mf * 16 + g;
#pragma unroll
        for (int kc = 0; kc < 4; kc++) {
            const int k0 = kc * 16 + 2 * tq;
            float2 p0 = *reinterpret_cast<const float2*>(&Zs[r0 * 68 + k0]);
            float2 p1 = *reinterpret_cast<const float2*>(&Zs[(r0 + 8) * 68 + k0]);
            float2 p2 = *reinterpret_cast<const float2*>(&Zs[r0 * 68 + k0 + 8]);
            float2 p3 = *reinterpret_cast<const float2*>(&Zs[(r0 + 8) * 68 + k0 + 8]);
            split_pair(p0.x, p0.y, ah[mf][kc][0], al[mf][kc][0]);
            split_pair(p1.x, p1.y, ah[mf][kc][1], al[mf][kc][1]);
            split_pair(p2.x, p2.y, ah[mf][kc][2], al[mf][kc][2]);
            split_pair(p3.x, p3.y, ah[mf][kc][3], al[mf][kc][3]);
        }
    }
    __syncthreads();

    float zsqv[4];
#pragma unroll
    for (int ri = 0; ri < 4; ri++)
        zsqv[ri] = ZSQ[rw * 32 + (ri >> 1) * 16 + g + (ri & 1) * 8];

    float bv[4]; int bi[4];
#pragma unroll
    for (int ri = 0; ri < 4; ri++) { bv[ri] = 3.4e38f; bi[ri] = 0; }

    const int swz = ((g & 3) << 3) ^ (g & 4);   // per-lane B k-swizzle

    for (int t = 0; t < NTILES; t++) {
        if (t >= NTILES - 2) { CP_WAIT0(); } else { CP_WAIT1(); }
        __syncthreads();

        const float* B = reinterpret_cast<const float*>(sm + ((t & 1) ? SM_B1 : SM_B0));
        const float* EST = ES + (t & 1) * 128;

        float acc[2][8][4];
#pragma unroll
        for (int mf = 0; mf < 2; mf++)
#pragma unroll
            for (int nf = 0; nf < 8; nf++)
#pragma unroll
                for (int j = 0; j < 4; j++) acc[mf][nf][j] = 0.f;

#pragma unroll
        for (int kc = 0; kc < 4; kc++) {
            const int kx0 = (kc * 16 + 2 * tq) ^ swz;   // even, float2-aligned
#pragma unroll
            for (int nf = 0; nf < 8; nf++) {
                const int nb = (cg * 64 + nf * 8 + g) * 64;
                float2 p0 = *reinterpret_cast<const float2*>(&B[nb + kx0]);
                float2 p1 = *reinterpret_cast<const float2*>(&B[nb + (kx0 ^ 8)]);
                uint32_t bh0, bl0, bh1, bl1;
                split_pair(p0.x, p0.y, bh0, bl0);
                split_pair(p1.x, p1.y, bh1, bl1);
#pragma unroll
                for (int mf = 0; mf < 2; mf++) {
                    mma16(acc[mf][nf], ah[mf][kc], bh0, bh1);   // hh
                    mma16(acc[mf][nf], ah[mf][kc], bl0, bl1);   // hl
                    mma16(acc[mf][nf], al[mf][kc], bh0, bh1);   // lh
                }
            }
        }

        // ---- epilogue: d2 = fl(fl(zsq - 2 dot) + es), running min ----
        const int colT = t * BN + cg * 64;
#pragma unroll
        for (int nf = 0; nf < 8; nf++) {
            float2 ep2 = reinterpret_cast<const float2*>(EST)[cg * 32 + nf * 4 + tq];
#pragma unroll
            for (int mf = 0; mf < 2; mf++) {
#pragma unroll
                for (int j = 0; j < 4; j++) {
                    float es = (j & 1) ? ep2.y : ep2.x;
                    int ri = mf * 2 + (j >> 1);
                    float tt = fmaf(-2.0f, acc[mf][nf][j], zsqv[ri]);
                    float d2 = tt + es;
                    int col = colT + nf * 8 + 2 * tq + (j & 1);
                    if (d2 < bv[ri]) { bv[ri] = d2; bi[ri] = col; }
                }
            }
        }

        __syncthreads();

        // ---- issue cp.async for tile t+2 into the buffer just freed ----
        if (t + 2 < NTILES) {
            const uint32_t dbase = smb + ((t & 1) ? SM_B1 : SM_B0);
            const float* ebase = E + (size_t)(t + 2) * BN * DDIM;
#pragma unroll
            for (int i = 0; i < 8; i++) {
                int c  = tid + i * 256;
                int n  = c >> 4;
                int kq = (c & 15) * 4;
                cp16(dbase + (uint32_t)(bswz(n, kq) * 4), ebase + (size_t)n * DDIM + kq);
            }
            if (tid < 32)
                cp16(smb + SM_ES + (t & 1) * 512 + tid * 16,
                     g_esq + (size_t)(t + 2) * BN + tid * 4);
            CP_COMMIT();
        }
    }

    // ---- reduce across the 4 tq lanes sharing each row (tie -> lowest col) ----
#pragma unroll
    for (int ri = 0; ri < 4; ri++) {
        float v = bv[ri];
        int   x = bi[ri];
#pragma unroll
        for (int off = 1; off <= 2; off <<= 1) {
            float ov = __shfl_xor_sync(0xFFFFFFFFu, v, off);
            int   ox = __shfl_xor_sync(0xFFFFFFFFu, x, off);
            if (ov < v || (ov == v && ox < x)) { v = ov; x = ox; }
        }
        bv[ri] = v; bi[ri] = x;
    }
    if (tq == 0 && cg == 0) {
#pragma unroll
        for (int ri = 0; ri < 4; ri++) {
            int row = rw * 32 + (ri >> 1) * 16 + g + (ri & 1) * 8;
            RV[row] = bv[ri]; RI[row] = bi[ri];
        }
    }
    __syncthreads();
    if (tq == 0 && cg == 1) {
#pragma unroll
        for (int ri = 0; ri < 4; ri++) {
            int row = rw * 32 + (ri >> 1) * 16 + g + (ri & 1) * 8;
            float v0 = RV[row]; int i0 = RI[row];
            int win = (bv[ri] < v0 || (bv[ri] == v0 && bi[ri] < i0)) ? bi[ri] : i0;
            g_idx[rowBase + row] = win;
        }
    }
}

// ---------------------------------------------------------------------------
// Kernel 3: gather + partial loss + index-as-float
// ---------------------------------------------------------------------------
__global__ __launch_bounds__(256) void gather_loss_kernel(
    const float* __restrict__ Z, const float* __restrict__ E,
    float* __restrict__ out)
{
    __shared__ float red[256];
    const int tid  = threadIdx.x;
    const int gtid = blockIdx.x * blockDim.x + tid;

    float lsum = 0.f;
    const float4* Z4 = reinterpret_cast<const float4*>(Z);
    float4* O4 = reinterpret_cast<float4*>(out);

#pragma unroll
    for (int j = 0; j < 4; j++) {
        int f   = gtid * 4 + j;
        int row = f >> 4;
        int dc  = (f & 15);
        int idx = g_idx[row];
        const float4* E4 = reinterpret_cast<const float4*>(E + (size_t)idx * DDIM);
        float4 q = E4[dc];
        float4 z = Z4[f];
        O4[f] = q;
        float dx = z.x - q.x, dy = z.y - q.y, dz = z.z - q.z, dw = z.w - q.w;
        lsum += dx * dx + dy * dy + dz * dz + dw * dw;
    }

    if (gtid < NROWS) out[OUT_IDX + gtid] = (float)g_idx[gtid];

    red[tid] = lsum;
    __syncthreads();
    for (int s = 128; s > 0; s >>= 1) {
        if (tid < s) red[tid] += red[tid + s];
        __syncthreads();
    }
    if (tid == 0) g_partial[blockIdx.x] = red[0];
}

// ---------------------------------------------------------------------------
// Kernel 4: finalize losses
// ---------------------------------------------------------------------------
__global__ __launch_bounds__(512) void finalize_kernel(float* __restrict__ out) {
    __shared__ float red[512];
    int tid = threadIdx.x;
    red[tid] = g_partial[tid] + g_partial[tid + 512];
    __syncthreads();
    for (int s = 256; s > 0; s >>= 1) {
        if (tid < s) red[tid] += red[tid + s];
        __syncthreads();
    }
    if (tid == 0) {
        float loss = red[0] * (1.0f / (float)(NROWS * DDIM)); // N*D = 2^22, exact
        out[OUT_LOSS + 0] = loss;
        out[OUT_LOSS + 1] = loss;
    }
}

// ---------------------------------------------------------------------------
extern "C" void kernel_launch(void* const* d_in, const int* in_sizes, int n_in,
                              void* d_out, int out_size)
{
    const float* Z = (const float*)d_in[0];
    const float* E = (const float*)d_in[1];
    if (n_in >= 2 && in_sizes[0] == KEMB * DDIM && in_sizes[1] == NROWS * DDIM) {
        const float* t = Z; Z = E; E = t;
    }
    float* out = (float*)d_out;

    cudaFuncSetAttribute(vq_mma_kernel,
                         cudaFuncAttributeMaxDynamicSharedMemorySize, SMEM_TOTAL);

    esq_kernel<<<KEMB / 256, 256>>>(E);
    vq_mma_kernel<<<NROWS / BM, NTHREADS, SMEM_TOTAL>>>(Z, E);
    gather_loss_kernel<<<NPARTIAL, 256>>>(Z, E, out);
    finalize_kernel<<<1, 512>>>(out);
}